// round 7
// baseline (speedup 1.0000x reference)
#include <cuda_runtime.h>

#define D     256
#define NB    30
#define NP    32          // padded rows (multiple of 8)
#define NROW  8           // rows per thread
#define EG    240
#define BG    2048

// Precomputed folded input-MLP matrices
__device__ float g_Mgeo[5 * D];    // W_geo @ W_lot[0:256]
__device__ float g_Msem[11 * D];   // emb   @ W_lot[256:512]
__device__ float g_bias0[D];       // b_geo @ W_lot[0:256] + b_lot

// ---------------------------------------------------------------------------
__global__ void pre_kernel(const float* __restrict__ Wgeo,
                           const float* __restrict__ bgeo,
                           const float* __restrict__ emb,
                           const float* __restrict__ Wlot,
                           const float* __restrict__ blot)
{
    int c = threadIdx.x;
    int r = blockIdx.x;
    if (r < 5) {
        float a = 0.f;
        for (int j = 0; j < D; j++) a += Wgeo[r * D + j] * Wlot[j * D + c];
        g_Mgeo[r * D + c] = a;
    } else if (r < 16) {
        int s = r - 5;
        float a = 0.f;
        for (int j = 0; j < D; j++) a += emb[s * D + j] * Wlot[(D + j) * D + c];
        g_Msem[s * D + c] = a;
    } else {
        float a = blot[c];
        for (int j = 0; j < D; j++) a += bgeo[j] * Wlot[j * D + c];
        g_bias0[c] = a;
    }
}

// ---------------------------------------------------------------------------
// One CTA per graph. 256 threads: tid = rg*64 + cq.
// Thread (rg, cq) owns columns [4cq, 4cq+4) for rows [8rg, 8rg+8) (rows
// padded to 32; padded rows are kept at exactly 0 and never affect the
// per-graph max since all stored activations are >= 0).
// 4-col x 8-row blocking: each LDS.128 of h feeds 16 FMAs.
// ---------------------------------------------------------------------------
__global__ void __launch_bounds__(256, 2)
graph_kernel(const float* __restrict__ geometry,
             const int*   __restrict__ semantic,
             const int*   __restrict__ e_src,
             const int*   __restrict__ e_dst,
             const float* __restrict__ Wlot,
             const float* __restrict__ Wmp1, const float* __restrict__ bmp1,
             const float* __restrict__ Wmp2, const float* __restrict__ bmp2,
             const float* __restrict__ Wmp3, const float* __restrict__ bmp3,
             const float* __restrict__ Wagg, const float* __restrict__ bagg,
             const float* __restrict__ Wmu,  const float* __restrict__ bmu,
             const float* __restrict__ Wvar, const float* __restrict__ bvar,
             float* __restrict__ out)
{
    extern __shared__ float smem[];
    float* sh_h  = smem;                  // NP*D = 8192
    float* sh_xa = sh_h + NP * D;         // NP*D = 8192
    float* smax  = sh_xa + NP * D;        // 4*D  = 1024 (per-rg partial max)
    float* sh_g  = smax + 4 * D;          // 4*D  = 1024 (g0..g3)
    float* s_geo = sh_g + 4 * D;          // NB*5
    float* s_inv = s_geo + NB * 5;        // NB
    int*   s_sem = (int*)(s_inv + NB);    // NB
    int*   s_cnt = s_sem + NB;            // NB
    int*   s_off = s_cnt + NB;            // NB+1
    int*   s_cur = s_off + NB + 1;        // NB
    int*   s_list = s_cur + NB;           // EG

    const int g   = blockIdx.x;
    const int tid = threadIdx.x;
    const int cq  = tid & 63;
    const int rg  = tid >> 6;
    const int c0  = 4 * cq;
    const int r0  = rg * NROW;

    // ---- load per-graph data, count degrees, build CSR ----
    for (int i = tid; i < NB * 5; i += 256) s_geo[i] = geometry[g * NB * 5 + i];
    if (tid < NB) { s_sem[tid] = semantic[g * NB + tid]; s_cnt[tid] = 0; }
    __syncthreads();
    if (tid < EG) {
        int d = e_dst[g * EG + tid] - g * NB;
        atomicAdd(&s_cnt[d], 1);
    }
    __syncthreads();
    if (tid == 0) {
        int a = 0;
        for (int i = 0; i < NB; i++) { s_off[i] = a; s_cur[i] = a; a += s_cnt[i]; }
        s_off[NB] = a;
    }
    if (tid < NB) s_inv[tid] = s_cnt[tid] ? 1.0f / (float)s_cnt[tid] : 0.0f;
    __syncthreads();
    if (tid < EG) {
        int s = e_src[g * EG + tid] - g * NB;
        int d = e_dst[g * EG + tid] - g * NB;
        int p = atomicAdd(&s_cur[d], 1);
        s_list[p] = s;
    }

    // ---- h0 = relu(geo@Mgeo + Msem[sem] + W_lot_pos + bias0), 4 cols x 8 rows
    {
        float4 mg[5];
        #pragma unroll
        for (int j = 0; j < 5; j++) mg[j] = *(const float4*)(g_Mgeo + j * D + c0);
        const float4 b0 = *(const float4*)(g_bias0 + c0);
        float4 pm = make_float4(0.f, 0.f, 0.f, 0.f);
        #pragma unroll
        for (int i = 0; i < NROW; i++) {
            int n = r0 + i;
            float4 v = make_float4(0.f, 0.f, 0.f, 0.f);
            if (n < NB) {
                float4 wl = *(const float4*)(Wlot + (2 * D + n) * D + c0);
                float4 ms = *(const float4*)(g_Msem + s_sem[n] * D + c0);
                v = make_float4(b0.x + wl.x + ms.x, b0.y + wl.y + ms.y,
                                b0.z + wl.z + ms.z, b0.w + wl.w + ms.w);
                #pragma unroll
                for (int j = 0; j < 5; j++) {
                    float ge = s_geo[n * 5 + j];
                    v.x = fmaf(ge, mg[j].x, v.x);
                    v.y = fmaf(ge, mg[j].y, v.y);
                    v.z = fmaf(ge, mg[j].z, v.z);
                    v.w = fmaf(ge, mg[j].w, v.w);
                }
                v.x = fmaxf(v.x, 0.f); v.y = fmaxf(v.y, 0.f);
                v.z = fmaxf(v.z, 0.f); v.w = fmaxf(v.w, 0.f);
            }
            *(float4*)(sh_h + n * D + c0) = v;
            pm.x = fmaxf(pm.x, v.x); pm.y = fmaxf(pm.y, v.y);
            pm.z = fmaxf(pm.z, v.z); pm.w = fmaxf(pm.w, v.w);
        }
        *(float4*)(smax + rg * D + c0) = pm;
    }
    __syncthreads();   // h0, smax, CSR visible
    sh_g[0 * D + tid] = fmaxf(fmaxf(smax[tid], smax[D + tid]),
                              fmaxf(smax[2 * D + tid], smax[3 * D + tid]));

    // ---- 3 message-passing layers ----
    const float* Wms[3] = { Wmp1, Wmp2, Wmp3 };
    const float* bms[3] = { bmp1, bmp2, bmp3 };

    for (int l = 0; l < 3; l++) {
        // gather: xa[n] = mean_{src in N(n)} h[src], 4 cols
        #pragma unroll
        for (int i = 0; i < NROW; i++) {
            int n = r0 + i;
            float4 a = make_float4(0.f, 0.f, 0.f, 0.f);
            if (n < NB) {
                int e1 = s_off[n + 1];
                for (int e = s_off[n]; e < e1; e++) {
                    float4 hv = *(const float4*)(sh_h + s_list[e] * D + c0);
                    a.x += hv.x; a.y += hv.y; a.z += hv.z; a.w += hv.w;
                }
                float inv = s_inv[n];
                a.x *= inv; a.y *= inv; a.z *= inv; a.w *= inv;
            }
            *(float4*)(sh_xa + n * D + c0) = a;
        }
        __syncthreads();

        // GEMM: C[n][c0..c0+3] = b + h[n]@W1 + xa[n]@W2
        const float* W  = Wms[l];
        const float4 bm = *(const float4*)(bms[l] + c0);
        float4 acc[NROW];
        #pragma unroll
        for (int i = 0; i < NROW; i++) acc[i] = bm;

        #pragma unroll
        for (int part = 0; part < 2; part++) {
            const float* A  = (part ? sh_xa : sh_h) + r0 * D;
            const float* Wb = W + part * D * D;
            for (int k4 = 0; k4 < D; k4 += 4) {
                float4 w0 = *(const float4*)(Wb + (k4 + 0) * D + c0);
                float4 w1 = *(const float4*)(Wb + (k4 + 1) * D + c0);
                float4 w2 = *(const float4*)(Wb + (k4 + 2) * D + c0);
                float4 w3 = *(const float4*)(Wb + (k4 + 3) * D + c0);
                #pragma unroll
                for (int i = 0; i < NROW; i++) {
                    float4 hv = *(const float4*)(A + i * D + k4);
                    float4 a = acc[i];
                    a.x = fmaf(hv.x, w0.x, a.x); a.y = fmaf(hv.x, w0.y, a.y);
                    a.z = fmaf(hv.x, w0.z, a.z); a.w = fmaf(hv.x, w0.w, a.w);
                    a.x = fmaf(hv.y, w1.x, a.x); a.y = fmaf(hv.y, w1.y, a.y);
                    a.z = fmaf(hv.y, w1.z, a.z); a.w = fmaf(hv.y, w1.w, a.w);
                    a.x = fmaf(hv.z, w2.x, a.x); a.y = fmaf(hv.z, w2.y, a.y);
                    a.z = fmaf(hv.z, w2.z, a.z); a.w = fmaf(hv.z, w2.w, a.w);
                    a.x = fmaf(hv.w, w3.x, a.x); a.y = fmaf(hv.w, w3.y, a.y);
                    a.z = fmaf(hv.w, w3.z, a.z); a.w = fmaf(hv.w, w3.w, a.w);
                    acc[i] = a;
                }
            }
        }
        __syncthreads();   // all reads of sh_h / sh_xa done

        float4 pm = make_float4(0.f, 0.f, 0.f, 0.f);
        #pragma unroll
        for (int i = 0; i < NROW; i++) {
            int n = r0 + i;
            float4 v = make_float4(0.f, 0.f, 0.f, 0.f);
            if (n < NB && s_cnt[n]) {      // cnt=0 (and padded rows) -> exact 0
                v.x = fmaxf(acc[i].x, 0.f); v.y = fmaxf(acc[i].y, 0.f);
                v.z = fmaxf(acc[i].z, 0.f); v.w = fmaxf(acc[i].w, 0.f);
            }
            *(float4*)(sh_h + n * D + c0) = v;
            pm.x = fmaxf(pm.x, v.x); pm.y = fmaxf(pm.y, v.y);
            pm.z = fmaxf(pm.z, v.z); pm.w = fmaxf(pm.w, v.w);
        }
        *(float4*)(smax + rg * D + c0) = pm;
        __syncthreads();
        sh_g[(l + 1) * D + tid] = fmaxf(fmaxf(smax[tid], smax[D + tid]),
                                        fmaxf(smax[2 * D + tid], smax[3 * D + tid]));
    }
    __syncthreads();   // sh_g complete

    // ---- readout: latent = [g0|g1|g2|g3] @ Wagg + bagg ----
    float lat = bagg[tid];
    for (int j = 0; j < 4 * D; j += 4) {
        float4 gv = *(const float4*)(sh_g + j);
        lat = fmaf(gv.x, Wagg[(j + 0) * D + tid], lat);
        lat = fmaf(gv.y, Wagg[(j + 1) * D + tid], lat);
        lat = fmaf(gv.z, Wagg[(j + 2) * D + tid], lat);
        lat = fmaf(gv.w, Wagg[(j + 3) * D + tid], lat);
    }
    smax[tid] = lat;
    __syncthreads();

    float mu = bmu[tid], lv = bvar[tid];
    for (int j = 0; j < D; j += 4) {
        float4 L = *(const float4*)(smax + j);
        mu = fmaf(L.x, Wmu[(j + 0) * D + tid], mu);
        mu = fmaf(L.y, Wmu[(j + 1) * D + tid], mu);
        mu = fmaf(L.z, Wmu[(j + 2) * D + tid], mu);
        mu = fmaf(L.w, Wmu[(j + 3) * D + tid], mu);
        lv = fmaf(L.x, Wvar[(j + 0) * D + tid], lv);
        lv = fmaf(L.y, Wvar[(j + 1) * D + tid], lv);
        lv = fmaf(L.z, Wvar[(j + 2) * D + tid], lv);
        lv = fmaf(L.w, Wvar[(j + 3) * D + tid], lv);
    }
    out[g * D + tid]          = mu;
    out[BG * D + g * D + tid] = lv;
}

// ---------------------------------------------------------------------------
extern "C" void kernel_launch(void* const* d_in, const int* in_sizes, int n_in,
                              void* d_out, int out_size)
{
    const float* geometry = (const float*)d_in[0];
    const int*   semantic = (const int*)d_in[1];
    const int*   eidx     = (const int*)d_in[2];
    const float* Wgeo = (const float*)d_in[4];
    const float* bgeo = (const float*)d_in[5];
    const float* emb  = (const float*)d_in[6];
    const float* Wlot = (const float*)d_in[7];
    const float* blot = (const float*)d_in[8];
    const float* Wmp1 = (const float*)d_in[9];
    const float* bmp1 = (const float*)d_in[10];
    const float* Wmp2 = (const float*)d_in[11];
    const float* bmp2 = (const float*)d_in[12];
    const float* Wmp3 = (const float*)d_in[13];
    const float* bmp3 = (const float*)d_in[14];
    const float* Wagg = (const float*)d_in[15];
    const float* bagg = (const float*)d_in[16];
    const float* Wmu  = (const float*)d_in[17];
    const float* bmu  = (const float*)d_in[18];
    const float* Wvar = (const float*)d_in[19];
    const float* bvar = (const float*)d_in[20];

    const int n_edges = in_sizes[2] / 2;
    const int* e_src = eidx;
    const int* e_dst = eidx + n_edges;

    pre_kernel<<<17, 256>>>(Wgeo, bgeo, emb, Wlot, blot);

    size_t smem_bytes = (2 * NP * D + 8 * D + NB * 5 + NB) * sizeof(float)
                      + (3 * NB + 1 + EG) * sizeof(int) + 64;
    cudaFuncSetAttribute(graph_kernel, cudaFuncAttributeMaxDynamicSharedMemorySize,
                         (int)smem_bytes);

    graph_kernel<<<BG, 256, smem_bytes>>>(
        geometry, semantic, e_src, e_dst, Wlot,
        Wmp1, bmp1, Wmp2, bmp2, Wmp3, bmp3,
        Wagg, bagg, Wmu, bmu, Wvar, bvar,
        (float*)d_out);
}

// round 8
// speedup vs baseline: 1.2361x; 1.2361x over previous
#include <cuda_runtime.h>

#define D     256
#define NB    30
#define NP    32      // padded rows
#define RT    16      // rows per thread
#define EG    240
#define BG    2048
#define GAUX  32      // graphs per aux CTA

// Precomputed folded input-MLP matrices
__device__ float g_Mgeo[5 * D];
__device__ float g_Msem[11 * D];
__device__ float g_bias0[D];
// pooled per-graph features [g][4*256]
__device__ float g_gbuf[BG * 4 * D];

// ---------------------------------------------------------------------------
__global__ void pre_kernel(const float* __restrict__ Wgeo,
                           const float* __restrict__ bgeo,
                           const float* __restrict__ emb,
                           const float* __restrict__ Wlot,
                           const float* __restrict__ blot)
{
    int c = threadIdx.x;
    int r = blockIdx.x;
    float a0 = 0.f, a1 = 0.f, a2 = 0.f, a3 = 0.f;
    if (r < 5) {
        for (int j = 0; j < D; j += 4) {
            a0 = fmaf(Wgeo[r * D + j + 0], Wlot[(j + 0) * D + c], a0);
            a1 = fmaf(Wgeo[r * D + j + 1], Wlot[(j + 1) * D + c], a1);
            a2 = fmaf(Wgeo[r * D + j + 2], Wlot[(j + 2) * D + c], a2);
            a3 = fmaf(Wgeo[r * D + j + 3], Wlot[(j + 3) * D + c], a3);
        }
        g_Mgeo[r * D + c] = (a0 + a1) + (a2 + a3);
    } else if (r < 16) {
        int s = r - 5;
        for (int j = 0; j < D; j += 4) {
            a0 = fmaf(emb[s * D + j + 0], Wlot[(D + j + 0) * D + c], a0);
            a1 = fmaf(emb[s * D + j + 1], Wlot[(D + j + 1) * D + c], a1);
            a2 = fmaf(emb[s * D + j + 2], Wlot[(D + j + 2) * D + c], a2);
            a3 = fmaf(emb[s * D + j + 3], Wlot[(D + j + 3) * D + c], a3);
        }
        g_Msem[s * D + c] = (a0 + a1) + (a2 + a3);
    } else {
        for (int j = 0; j < D; j += 4) {
            a0 = fmaf(bgeo[j + 0], Wlot[(j + 0) * D + c], a0);
            a1 = fmaf(bgeo[j + 1], Wlot[(j + 1) * D + c], a1);
            a2 = fmaf(bgeo[j + 2], Wlot[(j + 2) * D + c], a2);
            a3 = fmaf(bgeo[j + 3], Wlot[(j + 3) * D + c], a3);
        }
        g_bias0[c] = blot[c] + (a0 + a1) + (a2 + a3);
    }
}

// ---------------------------------------------------------------------------
// One CTA per graph. 128 threads: tid = rg*64 + cq.
// Thread (rg, cq) owns cols [4cq, 4cq+4) x rows [16rg, 16rg+16).
// C=4 x R=16 blocking: 0.125 L1-wavefronts per FMA-inst (vs 0.192 in the
// 2x15 config) -- each broadcast LDS.128 of h feeds 16 FMAs, each W value
// is loaded by only 2 row-groups (second one L1-hits).
// ---------------------------------------------------------------------------
__global__ void __launch_bounds__(128, 3)
graph_kernel(const float* __restrict__ geometry,
             const int*   __restrict__ semantic,
             const int*   __restrict__ e_src,
             const int*   __restrict__ e_dst,
             const float* __restrict__ Wlot,
             const float* __restrict__ Wmp1, const float* __restrict__ bmp1,
             const float* __restrict__ Wmp2, const float* __restrict__ bmp2,
             const float* __restrict__ Wmp3, const float* __restrict__ bmp3)
{
    extern __shared__ float smem[];
    float* sh_h  = smem;                  // NP*D = 8192
    float* sh_xa = sh_h + NP * D;         // NP*D = 8192
    float* smax  = sh_xa + NP * D;        // 2*D (per row-group partial max)
    float* s_geo = smax + 2 * D;          // NB*5
    float* s_inv = s_geo + NB * 5;        // NB
    int*   s_sem = (int*)(s_inv + NB);    // NB
    int*   s_cnt = s_sem + NB;            // NB
    int*   s_off = s_cnt + NB;            // NB+1
    int*   s_cur = s_off + NB + 1;        // NB
    int*   s_list = s_cur + NB;           // EG

    const int g   = blockIdx.x;
    const int tid = threadIdx.x;
    const int cq  = tid & 63;
    const int rg  = tid >> 6;
    const int c0  = 4 * cq;
    const int r0  = rg * RT;

    // ---- per-graph data, degrees, CSR ----
    for (int i = tid; i < NB * 5; i += 128) s_geo[i] = geometry[g * NB * 5 + i];
    if (tid < NB) { s_sem[tid] = semantic[g * NB + tid]; s_cnt[tid] = 0; }
    __syncthreads();
    for (int e = tid; e < EG; e += 128) {
        int d = e_dst[g * EG + e] - g * NB;
        atomicAdd(&s_cnt[d], 1);
    }
    __syncthreads();
    if (tid == 0) {
        int a = 0;
        for (int i = 0; i < NB; i++) { s_off[i] = a; s_cur[i] = a; a += s_cnt[i]; }
        s_off[NB] = a;
    }
    if (tid < NB) s_inv[tid] = s_cnt[tid] ? 1.0f / (float)s_cnt[tid] : 0.0f;
    __syncthreads();
    for (int e = tid; e < EG; e += 128) {
        int s = e_src[g * EG + e] - g * NB;
        int d = e_dst[g * EG + e] - g * NB;
        int p = atomicAdd(&s_cur[d], 1);
        s_list[p] = s;
    }

    // ---- h0 ----
    {
        float4 mg[5];
        #pragma unroll
        for (int j = 0; j < 5; j++) mg[j] = *(const float4*)(g_Mgeo + j * D + c0);
        const float4 b0 = *(const float4*)(g_bias0 + c0);
        float4 pm = make_float4(0.f, 0.f, 0.f, 0.f);
        #pragma unroll
        for (int i = 0; i < RT; i++) {
            int n = r0 + i;
            float4 v = make_float4(0.f, 0.f, 0.f, 0.f);
            if (n < NB) {
                float4 wl = *(const float4*)(Wlot + (2 * D + n) * D + c0);
                float4 ms = *(const float4*)(g_Msem + s_sem[n] * D + c0);
                v = make_float4(b0.x + wl.x + ms.x, b0.y + wl.y + ms.y,
                                b0.z + wl.z + ms.z, b0.w + wl.w + ms.w);
                #pragma unroll
                for (int j = 0; j < 5; j++) {
                    float ge = s_geo[n * 5 + j];
                    v.x = fmaf(ge, mg[j].x, v.x);
                    v.y = fmaf(ge, mg[j].y, v.y);
                    v.z = fmaf(ge, mg[j].z, v.z);
                    v.w = fmaf(ge, mg[j].w, v.w);
                }
                v.x = fmaxf(v.x, 0.f); v.y = fmaxf(v.y, 0.f);
                v.z = fmaxf(v.z, 0.f); v.w = fmaxf(v.w, 0.f);
            }
            *(float4*)(sh_h + n * D + c0) = v;
            pm.x = fmaxf(pm.x, v.x); pm.y = fmaxf(pm.y, v.y);
            pm.z = fmaxf(pm.z, v.z); pm.w = fmaxf(pm.w, v.w);
        }
        *(float4*)(smax + rg * D + c0) = pm;
    }
    __syncthreads();
    g_gbuf[g * 1024 + 0 * D + tid]       = fmaxf(smax[tid], smax[D + tid]);
    g_gbuf[g * 1024 + 0 * D + tid + 128] = fmaxf(smax[tid + 128], smax[D + tid + 128]);

    // ---- 3 message-passing layers ----
    const float* Wms[3] = { Wmp1, Wmp2, Wmp3 };
    const float* bms[3] = { bmp1, bmp2, bmp3 };

    for (int l = 0; l < 3; l++) {
        // gather
        #pragma unroll
        for (int i = 0; i < RT; i++) {
            int n = r0 + i;
            float4 a = make_float4(0.f, 0.f, 0.f, 0.f);
            if (n < NB) {
                int e1 = s_off[n + 1];
                for (int e = s_off[n]; e < e1; e++) {
                    float4 hv = *(const float4*)(sh_h + s_list[e] * D + c0);
                    a.x += hv.x; a.y += hv.y; a.z += hv.z; a.w += hv.w;
                }
                float inv = s_inv[n];
                a.x *= inv; a.y *= inv; a.z *= inv; a.w *= inv;
            }
            *(float4*)(sh_xa + n * D + c0) = a;
        }
        __syncthreads();

        // GEMM: C[n][c0..c0+3] = b + h[n]@W1 + xa[n]@W2
        const float* W  = Wms[l];
        const float4 bm = *(const float4*)(bms[l] + c0);
        float4 acc[RT];
        #pragma unroll
        for (int i = 0; i < RT; i++) acc[i] = bm;

        #pragma unroll
        for (int part = 0; part < 2; part++) {
            const float* A  = (part ? sh_xa : sh_h) + r0 * D;
            const float* Wb = W + part * D * D;
            for (int k4 = 0; k4 < D; k4 += 4) {
                float4 w0 = *(const float4*)(Wb + (k4 + 0) * D + c0);
                float4 w1 = *(const float4*)(Wb + (k4 + 1) * D + c0);
                float4 w2 = *(const float4*)(Wb + (k4 + 2) * D + c0);
                float4 w3 = *(const float4*)(Wb + (k4 + 3) * D + c0);
                #pragma unroll
                for (int i = 0; i < RT; i++) {
                    float4 hv = *(const float4*)(A + i * D + k4);
                    float4 a = acc[i];
                    a.x = fmaf(hv.x, w0.x, a.x); a.y = fmaf(hv.x, w0.y, a.y);
                    a.z = fmaf(hv.x, w0.z, a.z); a.w = fmaf(hv.x, w0.w, a.w);
                    a.x = fmaf(hv.y, w1.x, a.x); a.y = fmaf(hv.y, w1.y, a.y);
                    a.z = fmaf(hv.y, w1.z, a.z); a.w = fmaf(hv.y, w1.w, a.w);
                    a.x = fmaf(hv.z, w2.x, a.x); a.y = fmaf(hv.z, w2.y, a.y);
                    a.z = fmaf(hv.z, w2.z, a.z); a.w = fmaf(hv.z, w2.w, a.w);
                    a.x = fmaf(hv.w, w3.x, a.x); a.y = fmaf(hv.w, w3.y, a.y);
                    a.z = fmaf(hv.w, w3.z, a.z); a.w = fmaf(hv.w, w3.w, a.w);
                    acc[i] = a;
                }
            }
        }
        __syncthreads();   // all reads of sh_h / sh_xa done

        float4 pm = make_float4(0.f, 0.f, 0.f, 0.f);
        #pragma unroll
        for (int i = 0; i < RT; i++) {
            int n = r0 + i;
            float4 v = make_float4(0.f, 0.f, 0.f, 0.f);
            if (n < NB && s_cnt[n]) {      // cnt=0 / padded -> exact 0
                v.x = fmaxf(acc[i].x, 0.f); v.y = fmaxf(acc[i].y, 0.f);
                v.z = fmaxf(acc[i].z, 0.f); v.w = fmaxf(acc[i].w, 0.f);
            }
            *(float4*)(sh_h + n * D + c0) = v;
            pm.x = fmaxf(pm.x, v.x); pm.y = fmaxf(pm.y, v.y);
            pm.z = fmaxf(pm.z, v.z); pm.w = fmaxf(pm.w, v.w);
        }
        *(float4*)(smax + rg * D + c0) = pm;
        __syncthreads();
        g_gbuf[g * 1024 + (l + 1) * D + tid]       = fmaxf(smax[tid], smax[D + tid]);
        g_gbuf[g * 1024 + (l + 1) * D + tid + 128] = fmaxf(smax[tid + 128], smax[D + tid + 128]);
    }
}

// ---------------------------------------------------------------------------
// Readout: latent = g @ Wagg + b; mu/logvar = latent @ Wmu/Wvar + b.
// 32 graphs per CTA so the 1.5 MB of readout weights is read 64x total
// instead of 2048x (removes ~3 GB of L2 traffic from the main kernel).
// ---------------------------------------------------------------------------
__global__ void __launch_bounds__(256)
aux_kernel(const float* __restrict__ Wagg, const float* __restrict__ bagg,
           const float* __restrict__ Wmu,  const float* __restrict__ bmu,
           const float* __restrict__ Wvar, const float* __restrict__ bvar,
           float* __restrict__ out)
{
    __shared__ float sh_lat[GAUX * D];
    const int c  = threadIdx.x;
    const int g0 = blockIdx.x * GAUX;

    float lat[GAUX];
    {
        float bg = bagg[c];
        #pragma unroll
        for (int i = 0; i < GAUX; i++) lat[i] = bg;
    }
    for (int k4 = 0; k4 < 4 * D; k4 += 4) {
        float w0 = Wagg[(k4 + 0) * D + c];
        float w1 = Wagg[(k4 + 1) * D + c];
        float w2 = Wagg[(k4 + 2) * D + c];
        float w3 = Wagg[(k4 + 3) * D + c];
        #pragma unroll 8
        for (int i = 0; i < GAUX; i++) {
            float4 gv = *(const float4*)(g_gbuf + (g0 + i) * 1024 + k4);
            lat[i] = fmaf(gv.x, w0, fmaf(gv.y, w1, fmaf(gv.z, w2, fmaf(gv.w, w3, lat[i]))));
        }
    }
    #pragma unroll
    for (int i = 0; i < GAUX; i++) sh_lat[i * D + c] = lat[i];
    __syncthreads();

    float mu[GAUX], lv[GAUX];
    {
        float bm_ = bmu[c], bv_ = bvar[c];
        #pragma unroll
        for (int i = 0; i < GAUX; i++) { mu[i] = bm_; lv[i] = bv_; }
    }
    for (int j4 = 0; j4 < D; j4 += 4) {
        float m0 = Wmu[(j4 + 0) * D + c],  m1 = Wmu[(j4 + 1) * D + c];
        float m2 = Wmu[(j4 + 2) * D + c],  m3 = Wmu[(j4 + 3) * D + c];
        float v0 = Wvar[(j4 + 0) * D + c], v1 = Wvar[(j4 + 1) * D + c];
        float v2 = Wvar[(j4 + 2) * D + c], v3 = Wvar[(j4 + 3) * D + c];
        #pragma unroll 8
        for (int i = 0; i < GAUX; i++) {
            float4 L = *(const float4*)(sh_lat + i * D + j4);
            mu[i] = fmaf(L.x, m0, fmaf(L.y, m1, fmaf(L.z, m2, fmaf(L.w, m3, mu[i]))));
            lv[i] = fmaf(L.x, v0, fmaf(L.y, v1, fmaf(L.z, v2, fmaf(L.w, v3, lv[i]))));
        }
    }
    #pragma unroll
    for (int i = 0; i < GAUX; i++) {
        out[(g0 + i) * D + c]          = mu[i];
        out[BG * D + (g0 + i) * D + c] = lv[i];
    }
}

// ---------------------------------------------------------------------------
extern "C" void kernel_launch(void* const* d_in, const int* in_sizes, int n_in,
                              void* d_out, int out_size)
{
    const float* geometry = (const float*)d_in[0];
    const int*   semantic = (const int*)d_in[1];
    const int*   eidx     = (const int*)d_in[2];
    const float* Wgeo = (const float*)d_in[4];
    const float* bgeo = (const float*)d_in[5];
    const float* emb  = (const float*)d_in[6];
    const float* Wlot = (const float*)d_in[7];
    const float* blot = (const float*)d_in[8];
    const float* Wmp1 = (const float*)d_in[9];
    const float* bmp1 = (const float*)d_in[10];
    const float* Wmp2 = (const float*)d_in[11];
    const float* bmp2 = (const float*)d_in[12];
    const float* Wmp3 = (const float*)d_in[13];
    const float* bmp3 = (const float*)d_in[14];
    const float* Wagg = (const float*)d_in[15];
    const float* bagg = (const float*)d_in[16];
    const float* Wmu  = (const float*)d_in[17];
    const float* bmu  = (const float*)d_in[18];
    const float* Wvar = (const float*)d_in[19];
    const float* bvar = (const float*)d_in[20];

    const int n_edges = in_sizes[2] / 2;
    const int* e_src = eidx;
    const int* e_dst = eidx + n_edges;

    pre_kernel<<<17, 256>>>(Wgeo, bgeo, emb, Wlot, blot);

    size_t smem_bytes = (2 * NP * D + 2 * D + NB * 5 + NB) * sizeof(float)
                      + (3 * NB + 1 + EG) * sizeof(int) + 64;
    cudaFuncSetAttribute(graph_kernel, cudaFuncAttributeMaxDynamicSharedMemorySize,
                         (int)smem_bytes);

    graph_kernel<<<BG, 128, smem_bytes>>>(
        geometry, semantic, e_src, e_dst, Wlot,
        Wmp1, bmp1, Wmp2, bmp2, Wmp3, bmp3);

    aux_kernel<<<BG / GAUX, 256>>>(Wagg, bagg, Wmu, bmu, Wvar, bvar, (float*)d_out);
}